// round 4
// baseline (speedup 1.0000x reference)
#include <cuda_runtime.h>
#include <math.h>

#define GCTA    128
#define T_STEPS 2048
#define BATCH   32
#define HDIM    512
#define DIN     256

// ---- scratch (device globals; no allocation allowed) ----
__device__ float g_xw[(size_t)T_STEPS * HDIM * BATCH];   // [t][j][b], 134MB
__device__ float g_h[2][HDIM * BATCH];                   // ping-pong hidden state, [j][b]
__device__ float g_qh[BATCH * HDIM];                     // KW @ Q0
__device__ float g_sc[BATCH * T_STEPS];                  // scores
__device__ float g_att[BATCH * T_STEPS];                 // softmax weights
__device__ float g_cpart[8][BATCH * HDIM];               // context partials
// barrier state: arrive counter and release epoch on SEPARATE cache lines
__device__ __align__(128) unsigned g_arrive;
__device__ __align__(128) unsigned g_epoch;

// ---------------------------------------------------------------------------
__global__ void init_kernel() {
    int idx = blockIdx.x * blockDim.x + threadIdx.x;
    if (idx < HDIM * BATCH) g_h[0][idx] = 0.f;
    if (idx == 0) { g_arrive = 0u; g_epoch = 0u; }
}

__global__ void dummy_kernel() {}   // launch-position filler so ncu -s 5 lands on rnn_loop

// ---------------------------------------------------------------------------
// xw[t][j][b] = sum_d X[b][t][d] * Wxh[d][j]
// grid (T, 16): CTA covers one t and 32 j columns. Two K-passes of 128.
__global__ __launch_bounds__(256) void xw_kernel(const float* __restrict__ X,
                                                 const float* __restrict__ Wxh) {
    __shared__ __align__(16) float Xs[128 * 33];  // [dl][b], padded
    __shared__ __align__(16) float Ws[128 * 32];  // [dl][jj]
    int t  = blockIdx.x;
    int j0 = blockIdx.y * 32;
    int tid = threadIdx.x;
    int warp = tid >> 5, lane = tid & 31;
    float acc0 = 0.f, acc1 = 0.f, acc2 = 0.f, acc3 = 0.f;

    for (int kp = 0; kp < 2; ++kp) {
        #pragma unroll
        for (int bb = 0; bb < 4; ++bb) {
            int b = warp * 4 + bb;
            const float* xp = X + ((size_t)b * T_STEPS + t) * DIN + kp * 128;
            #pragma unroll
            for (int it = 0; it < 4; ++it) {
                int dl = it * 32 + lane;
                Xs[dl * 33 + b] = xp[dl];
            }
        }
        for (int idx = tid; idx < 128 * 32; idx += 256) {
            int dl = idx >> 5, jj = idx & 31;
            Ws[idx] = Wxh[(size_t)(kp * 128 + dl) * HDIM + j0 + jj];
        }
        __syncthreads();
        #pragma unroll 8
        for (int dl = 0; dl < 128; ++dl) {
            float xv = Xs[dl * 33 + lane];
            float4 w = *(const float4*)&Ws[dl * 32 + warp * 4];
            acc0 += xv * w.x; acc1 += xv * w.y; acc2 += xv * w.z; acc3 += xv * w.w;
        }
        __syncthreads();
    }
    float* op = g_xw + ((size_t)t * HDIM + j0 + warp * 4) * BATCH + lane;
    op[0]  = acc0;
    op[32] = acc1;
    op[64] = acc2;
    op[96] = acc3;
}

// ---------------------------------------------------------------------------
// Persistent recurrence kernel. 128 CTAs, each owns 4 consecutive j columns.
// Per step: hout[j][b] = tanh( sum_i hin[i][b]*Whh[i][j] + xw[t][j][b] + bh[j] )
// Barrier: atomicAdd on g_arrive; LAST arriver publishes g_epoch (separate
// line). Spinners read g_epoch only — no RMW/read contention on one line.
__global__ __launch_bounds__(256) void rnn_loop(const float* __restrict__ Whh,
                                                const float* __restrict__ bh,
                                                float* __restrict__ Y) {
    __shared__ __align__(16) float Ws[HDIM * 4];    // Whh[:, j0..j0+3], [i][c]
    __shared__ __align__(16) float red[8 * 32 * 4]; // [warp][b][c]
    int j0  = blockIdx.x * 4;
    int tid = threadIdx.x;
    for (int idx = tid; idx < HDIM * 4; idx += 256) {
        int i = idx >> 2, c = idx & 3;
        Ws[idx] = Whh[(size_t)i * HDIM + j0 + c];
    }
    int rb = tid >> 2, rc = tid & 3;  // reduction thread -> (b, c), tid < 128
    float bias = (tid < 128) ? bh[j0 + rc] : 0.f;
    int warp = tid >> 5, lane = tid & 31;
    int k0 = warp * 64;
    __syncthreads();

    // prefetch xw for step 0
    float xw_pref = (tid < 128) ? g_xw[((size_t)0 * HDIM + j0 + rc) * BATCH + rb] : 0.f;

    for (int t = 0; t < T_STEPS; ++t) {
        // ---- wait for previous step's release (epoch line, read-only) ----
        if (t > 0 && tid == 0) {
            while (*((volatile unsigned*)&g_epoch) < (unsigned)t) { }
            __threadfence();   // acquire: order epoch read before hin reads
        }
        __syncthreads();

        const float* hin = g_h[t & 1];
        float* hout = g_h[(t & 1) ^ 1];
        float a0 = 0.f, a1 = 0.f, a2 = 0.f, a3 = 0.f;
        const float* hp = hin + k0 * BATCH + lane;   // coalesced 128B rows
        const float4* wp = (const float4*)&Ws[k0 * 4];
        #pragma unroll 8
        for (int i = 0; i < 64; ++i) {
            float hv = __ldcg(hp + i * BATCH);
            float4 w = wp[i];
            a0 += hv * w.x; a1 += hv * w.y; a2 += hv * w.z; a3 += hv * w.w;
        }
        *(float4*)&red[tid * 4] = make_float4(a0, a1, a2, a3);
        __syncthreads();

        float hv_out = 0.f;
        if (tid < 128) {
            float s = bias + xw_pref;
            #pragma unroll
            for (int w = 0; w < 8; ++w) s += red[(w * 32 + rb) * 4 + rc];
            hv_out = tanhf(s);
            __stcg(&hout[(j0 + rc) * BATCH + rb], hv_out);
        }
        __syncthreads();

        // ---- arrive (release): counter on its own line ----
        if (tid == 0) {
            __threadfence();                 // publish hout stores to gpu scope
            unsigned old = atomicAdd(&g_arrive, 1u);
            if (old == (unsigned)(t + 1) * GCTA - 1u) {
                __threadfence();
                *((volatile unsigned*)&g_epoch) = (unsigned)(t + 1);
            }
        }

        // ---- off-critical-path: Y output + xw prefetch for t+1 ----
        if (tid < 128) {
            Y[(size_t)t * (BATCH * HDIM) + (size_t)rb * HDIM + j0 + rc] = hv_out;
            if (t + 1 < T_STEPS)
                xw_pref = g_xw[((size_t)(t + 1) * HDIM + j0 + rc) * BATCH + rb];
        }
    }
}

// ---------------------------------------------------------------------------
// Q0[b] = Y[T-1,b] @ QW ; Qh[b] = KW @ Q0[b]   (one CTA per b)
__global__ __launch_bounds__(256) void att_q_kernel(const float* __restrict__ Y,
                                                    const float* __restrict__ QW,
                                                    const float* __restrict__ KW) {
    __shared__ float yT[HDIM];
    __shared__ float q0s[DIN];
    int b = blockIdx.x, tid = threadIdx.x;
    for (int h = tid; h < HDIM; h += 256)
        yT[h] = Y[(size_t)(T_STEPS - 1) * BATCH * HDIM + (size_t)b * HDIM + h];
    __syncthreads();
    float s = 0.f;
    for (int h = 0; h < HDIM; ++h) s += yT[h] * QW[(size_t)h * DIN + tid];
    q0s[tid] = s;
    __syncthreads();
    for (int j = tid; j < HDIM; j += 256) {
        float s2 = 0.f;
        const float* kp = KW + (size_t)j * DIN;
        #pragma unroll 4
        for (int d = 0; d < DIN; ++d) s2 += kp[d] * q0s[d];
        g_qh[b * HDIM + j] = s2;
    }
}

// scores[b][t] = tanh( Y[t,b,:] . Qh[b,:] )
__global__ __launch_bounds__(256) void att_scores_kernel(const float* __restrict__ Y) {
    __shared__ float qh[HDIM];
    int b = blockIdx.y, t0 = blockIdx.x * 64, tid = threadIdx.x;
    for (int h = tid; h < HDIM; h += 256) qh[h] = g_qh[b * HDIM + h];
    __syncthreads();
    int warp = tid >> 5, lane = tid & 31;
    for (int tt = warp; tt < 64; tt += 8) {
        int t = t0 + tt;
        const float* yp = Y + (size_t)t * BATCH * HDIM + (size_t)b * HDIM;
        float s = 0.f;
        #pragma unroll
        for (int it = 0; it < 16; ++it) s += yp[it * 32 + lane] * qh[it * 32 + lane];
        #pragma unroll
        for (int off = 16; off > 0; off >>= 1) s += __shfl_xor_sync(0xffffffffu, s, off);
        if (lane == 0) g_sc[b * T_STEPS + t] = tanhf(s);
    }
}

__global__ __launch_bounds__(256) void att_softmax_kernel() {
    __shared__ float sred[256];
    int b = blockIdx.x, tid = threadIdx.x;
    const float* sp = g_sc + b * T_STEPS;
    float m = -1e30f;
    for (int t = tid; t < T_STEPS; t += 256) m = fmaxf(m, sp[t]);
    sred[tid] = m; __syncthreads();
    for (int o = 128; o > 0; o >>= 1) {
        if (tid < o) sred[tid] = fmaxf(sred[tid], sred[tid + o]);
        __syncthreads();
    }
    m = sred[0]; __syncthreads();
    float sum = 0.f;
    for (int t = tid; t < T_STEPS; t += 256) sum += expf(sp[t] - m);
    sred[tid] = sum; __syncthreads();
    for (int o = 128; o > 0; o >>= 1) {
        if (tid < o) sred[tid] += sred[tid + o];
        __syncthreads();
    }
    float inv = 1.f / sred[0];
    for (int t = tid; t < T_STEPS; t += 256)
        g_att[b * T_STEPS + t] = expf(sp[t] - m) * inv;
}

// c partials: grid (8 t-chunks, 32 b)
__global__ __launch_bounds__(256) void att_ctx_kernel(const float* __restrict__ Y) {
    __shared__ float As[256];
    int tc = blockIdx.x, b = blockIdx.y, tid = threadIdx.x;
    As[tid] = g_att[b * T_STEPS + tc * 256 + tid];
    __syncthreads();
    float acc0 = 0.f, acc1 = 0.f;
    for (int tt = 0; tt < 256; ++tt) {
        const float* yp = Y + (size_t)(tc * 256 + tt) * BATCH * HDIM + (size_t)b * HDIM;
        float a = As[tt];
        acc0 += a * yp[tid];
        acc1 += a * yp[tid + 256];
    }
    g_cpart[tc][b * HDIM + tid]        = acc0;
    g_cpart[tc][b * HDIM + tid + 256]  = acc1;
}

__global__ __launch_bounds__(512) void att_ctx2_kernel(float* __restrict__ out_c) {
    int b = blockIdx.x, tid = threadIdx.x;
    float s = 0.f;
    #pragma unroll
    for (int p = 0; p < 8; ++p) s += g_cpart[p][b * HDIM + tid];
    out_c[(size_t)b * HDIM + tid] = s;
}

// ---------------------------------------------------------------------------
extern "C" void kernel_launch(void* const* d_in, const int* in_sizes, int n_in,
                              void* d_out, int out_size) {
    const float* X   = (const float*)d_in[0];
    const float* Wxh = (const float*)d_in[1];
    const float* Whh = (const float*)d_in[2];
    const float* bh  = (const float*)d_in[3];
    const float* QW  = (const float*)d_in[4];
    const float* KW  = (const float*)d_in[5];
    float* Y = (float*)d_out;                                    // [T][B][H]
    float* out_c = Y + (size_t)T_STEPS * BATCH * HDIM;           // [B][H]

    init_kernel<<<64, 256>>>();
    xw_kernel<<<dim3(T_STEPS, 16), 256>>>(X, Wxh);
    dummy_kernel<<<1, 32>>>();     // position rnn_loop at the ncu capture slot
    rnn_loop<<<GCTA, 256>>>(Whh, bh, Y);
    att_q_kernel<<<BATCH, 256>>>(Y, QW, KW);
    att_scores_kernel<<<dim3(32, BATCH), 256>>>(Y);
    att_softmax_kernel<<<BATCH, 256>>>();
    att_ctx_kernel<<<dim3(8, BATCH), 256>>>(Y);
    att_ctx2_kernel<<<BATCH, 512>>>(out_c);
}

// round 5
// speedup vs baseline: 3.1366x; 3.1366x over previous
#include <cuda_runtime.h>
#include <math.h>

#define GCTA    64
#define RTHREADS 512
#define JPC     8
#define T_STEPS 2048
#define BATCH   32
#define HDIM    512
#define DIN     256

// ---- scratch (device globals; no allocation allowed) ----
__device__ float g_xw[(size_t)T_STEPS * HDIM * BATCH];   // [t][j][b], 134MB
__device__ float g_h[2][HDIM * BATCH];                   // ping-pong hidden state, [j][b]
__device__ float g_qh[BATCH * HDIM];                     // KW @ Q0
__device__ float g_sc[BATCH * T_STEPS];                  // scores
__device__ float g_att[BATCH * T_STEPS];                 // softmax weights
__device__ float g_cpart[8][BATCH * HDIM];               // context partials
__device__ __align__(128) unsigned g_arrive;             // arrive counter (own line)
__device__ __align__(128) unsigned g_mail[GCTA * 32];    // per-CTA mailboxes, 128B apart

// ---------------------------------------------------------------------------
__global__ void init_kernel() {
    int idx = blockIdx.x * blockDim.x + threadIdx.x;
    if (idx < HDIM * BATCH) g_h[0][idx] = 0.f;
    if (idx < GCTA) g_mail[idx * 32] = 0u;
    if (idx == 0) g_arrive = 0u;
}

__global__ void dummy_kernel() {}   // launch-position filler so ncu -s 5 lands on rnn_loop

// ---------------------------------------------------------------------------
// xw[t][j][b] = sum_d X[b][t][d] * Wxh[d][j]
__global__ __launch_bounds__(256) void xw_kernel(const float* __restrict__ X,
                                                 const float* __restrict__ Wxh) {
    __shared__ __align__(16) float Xs[128 * 33];  // [dl][b], padded
    __shared__ __align__(16) float Ws[128 * 32];  // [dl][jj]
    int t  = blockIdx.x;
    int j0 = blockIdx.y * 32;
    int tid = threadIdx.x;
    int warp = tid >> 5, lane = tid & 31;
    float acc0 = 0.f, acc1 = 0.f, acc2 = 0.f, acc3 = 0.f;

    for (int kp = 0; kp < 2; ++kp) {
        #pragma unroll
        for (int bb = 0; bb < 4; ++bb) {
            int b = warp * 4 + bb;
            const float* xp = X + ((size_t)b * T_STEPS + t) * DIN + kp * 128;
            #pragma unroll
            for (int it = 0; it < 4; ++it) {
                int dl = it * 32 + lane;
                Xs[dl * 33 + b] = xp[dl];
            }
        }
        for (int idx = tid; idx < 128 * 32; idx += 256) {
            int dl = idx >> 5, jj = idx & 31;
            Ws[idx] = Wxh[(size_t)(kp * 128 + dl) * HDIM + j0 + jj];
        }
        __syncthreads();
        #pragma unroll 8
        for (int dl = 0; dl < 128; ++dl) {
            float xv = Xs[dl * 33 + lane];
            float4 w = *(const float4*)&Ws[dl * 32 + warp * 4];
            acc0 += xv * w.x; acc1 += xv * w.y; acc2 += xv * w.z; acc3 += xv * w.w;
        }
        __syncthreads();
    }
    float* op = g_xw + ((size_t)t * HDIM + j0 + warp * 4) * BATCH + lane;
    op[0]  = acc0;
    op[32] = acc1;
    op[64] = acc2;
    op[96] = acc3;
}

// ---------------------------------------------------------------------------
// Persistent recurrence. 64 CTAs x 512 threads; CTA owns 8 consecutive j cols.
// Barrier: release-arrive on g_arrive; last arriver fans epoch out to 64
// PRIVATE mailboxes (one 128B line per CTA). Each CTA spins on its own line
// with relaxed loads — no shared-line contention anywhere.
__global__ __launch_bounds__(RTHREADS) void rnn_loop(const float* __restrict__ Whh,
                                                     const float* __restrict__ bh,
                                                     float* __restrict__ Y) {
    __shared__ __align__(16) float Ws[HDIM * JPC];        // Whh[:, j0..j0+7], [i][c], 16KB
    __shared__ __align__(16) float red[JPC * RTHREADS];   // [c][warp][lane], 16KB
    int j0  = blockIdx.x * JPC;
    int tid = threadIdx.x;
    for (int idx = tid; idx < HDIM * JPC; idx += RTHREADS) {
        int i = idx >> 3, c = idx & 7;
        Ws[idx] = Whh[(size_t)i * HDIM + j0 + c];
    }
    int rb = tid & 31, rc = tid >> 5;          // final-phase thread -> (b, c), tid < 256
    float bias = (tid < 256) ? bh[j0 + rc] : 0.f;
    int warp = tid >> 5, lane = tid & 31;
    int i0 = warp * 32;
    unsigned* mybox = &g_mail[blockIdx.x * 32];
    __syncthreads();

    float xw_pref = (tid < 256) ? g_xw[((size_t)0 * HDIM + j0 + rc) * BATCH + rb] : 0.f;

    for (int t = 0; t < T_STEPS; ++t) {
        // ---- wait on private mailbox ----
        if (t > 0) {
            if (tid == 0) {
                unsigned v;
                do {
                    asm volatile("ld.relaxed.gpu.global.u32 %0, [%1];"
                                 : "=r"(v) : "l"(mybox));
                } while (v < (unsigned)t);
                asm volatile("fence.acq_rel.gpu;" ::: "memory");
            }
            __syncthreads();
        }

        const float* hin = g_h[t & 1];
        float* hout = g_h[(t & 1) ^ 1];
        float a0=0.f,a1=0.f,a2=0.f,a3=0.f,a4=0.f,a5=0.f,a6=0.f,a7=0.f;
        const float* hp = hin + i0 * BATCH + lane;   // coalesced 128B rows
        #pragma unroll 8
        for (int i = 0; i < 32; ++i) {
            float hv = __ldcg(hp + i * BATCH);
            float4 w0 = *(const float4*)&Ws[(i0 + i) * JPC];
            float4 w1 = *(const float4*)&Ws[(i0 + i) * JPC + 4];
            a0 += hv * w0.x; a1 += hv * w0.y; a2 += hv * w0.z; a3 += hv * w0.w;
            a4 += hv * w1.x; a5 += hv * w1.y; a6 += hv * w1.z; a7 += hv * w1.w;
        }
        // conflict-free: red[c][warp][lane]
        red[0*RTHREADS + tid] = a0; red[1*RTHREADS + tid] = a1;
        red[2*RTHREADS + tid] = a2; red[3*RTHREADS + tid] = a3;
        red[4*RTHREADS + tid] = a4; red[5*RTHREADS + tid] = a5;
        red[6*RTHREADS + tid] = a6; red[7*RTHREADS + tid] = a7;
        __syncthreads();

        float hv_out = 0.f;
        if (tid < 256) {
            float s = bias + xw_pref;
            #pragma unroll
            for (int w = 0; w < 16; ++w) s += red[rc * RTHREADS + w * 32 + rb];
            hv_out = tanhf(s);
            __stcg(&hout[(j0 + rc) * BATCH + rb], hv_out);   // coalesced
        }
        __syncthreads();

        // ---- arrive (release) + distributed publish ----
        if (tid == 0) {
            asm volatile("fence.acq_rel.gpu;" ::: "memory");
            unsigned old = atomicAdd(&g_arrive, 1u);
            if (old == (unsigned)(t + 1) * GCTA - 1u) {
                asm volatile("fence.acq_rel.gpu;" ::: "memory");
                unsigned ep = (unsigned)(t + 1);
                #pragma unroll 8
                for (int m = 0; m < GCTA; ++m)
                    asm volatile("st.relaxed.gpu.global.u32 [%0], %1;"
                                 :: "l"(&g_mail[m * 32]), "r"(ep));
            }
        }

        // ---- off-critical-path: Y output + xw prefetch for t+1 ----
        if (tid < 256) {
            Y[(size_t)t * (BATCH * HDIM) + (size_t)rb * HDIM + j0 + rc] = hv_out;
            if (t + 1 < T_STEPS)
                xw_pref = g_xw[((size_t)(t + 1) * HDIM + j0 + rc) * BATCH + rb];
        }
    }
}

// ---------------------------------------------------------------------------
// Q0[b] = Y[T-1,b] @ QW ; Qh[b] = KW @ Q0[b]   (one CTA per b)
__global__ __launch_bounds__(256) void att_q_kernel(const float* __restrict__ Y,
                                                    const float* __restrict__ QW,
                                                    const float* __restrict__ KW) {
    __shared__ float yT[HDIM];
    __shared__ float q0s[DIN];
    int b = blockIdx.x, tid = threadIdx.x;
    for (int h = tid; h < HDIM; h += 256)
        yT[h] = Y[(size_t)(T_STEPS - 1) * BATCH * HDIM + (size_t)b * HDIM + h];
    __syncthreads();
    float s = 0.f;
    for (int h = 0; h < HDIM; ++h) s += yT[h] * QW[(size_t)h * DIN + tid];
    q0s[tid] = s;
    __syncthreads();
    for (int j = tid; j < HDIM; j += 256) {
        float s2 = 0.f;
        const float* kp = KW + (size_t)j * DIN;
        #pragma unroll 4
        for (int d = 0; d < DIN; ++d) s2 += kp[d] * q0s[d];
        g_qh[b * HDIM + j] = s2;
    }
}

// scores[b][t] = tanh( Y[t,b,:] . Qh[b,:] )
__global__ __launch_bounds__(256) void att_scores_kernel(const float* __restrict__ Y) {
    __shared__ float qh[HDIM];
    int b = blockIdx.y, t0 = blockIdx.x * 64, tid = threadIdx.x;
    for (int h = tid; h < HDIM; h += 256) qh[h] = g_qh[b * HDIM + h];
    __syncthreads();
    int warp = tid >> 5, lane = tid & 31;
    for (int tt = warp; tt < 64; tt += 8) {
        int t = t0 + tt;
        const float* yp = Y + (size_t)t * BATCH * HDIM + (size_t)b * HDIM;
        float s = 0.f;
        #pragma unroll
        for (int it = 0; it < 16; ++it) s += yp[it * 32 + lane] * qh[it * 32 + lane];
        #pragma unroll
        for (int off = 16; off > 0; off >>= 1) s += __shfl_xor_sync(0xffffffffu, s, off);
        if (lane == 0) g_sc[b * T_STEPS + t] = tanhf(s);
    }
}

__global__ __launch_bounds__(256) void att_softmax_kernel() {
    __shared__ float sred[256];
    int b = blockIdx.x, tid = threadIdx.x;
    const float* sp = g_sc + b * T_STEPS;
    float m = -1e30f;
    for (int t = tid; t < T_STEPS; t += 256) m = fmaxf(m, sp[t]);
    sred[tid] = m; __syncthreads();
    for (int o = 128; o > 0; o >>= 1) {
        if (tid < o) sred[tid] = fmaxf(sred[tid], sred[tid + o]);
        __syncthreads();
    }
    m = sred[0]; __syncthreads();
    float sum = 0.f;
    for (int t = tid; t < T_STEPS; t += 256) sum += expf(sp[t] - m);
    sred[tid] = sum; __syncthreads();
    for (int o = 128; o > 0; o >>= 1) {
        if (tid < o) sred[tid] += sred[tid + o];
        __syncthreads();
    }
    float inv = 1.f / sred[0];
    for (int t = tid; t < T_STEPS; t += 256)
        g_att[b * T_STEPS + t] = expf(sp[t] - m) * inv;
}

// c partials: grid (8 t-chunks, 32 b)
__global__ __launch_bounds__(256) void att_ctx_kernel(const float* __restrict__ Y) {
    __shared__ float As[256];
    int tc = blockIdx.x, b = blockIdx.y, tid = threadIdx.x;
    As[tid] = g_att[b * T_STEPS + tc * 256 + tid];
    __syncthreads();
    float acc0 = 0.f, acc1 = 0.f;
    for (int tt = 0; tt < 256; ++tt) {
        const float* yp = Y + (size_t)(tc * 256 + tt) * BATCH * HDIM + (size_t)b * HDIM;
        float a = As[tt];
        acc0 += a * yp[tid];
        acc1 += a * yp[tid + 256];
    }
    g_cpart[tc][b * HDIM + tid]        = acc0;
    g_cpart[tc][b * HDIM + tid + 256]  = acc1;
}

__global__ __launch_bounds__(512) void att_ctx2_kernel(float* __restrict__ out_c) {
    int b = blockIdx.x, tid = threadIdx.x;
    float s = 0.f;
    #pragma unroll
    for (int p = 0; p < 8; ++p) s += g_cpart[p][b * HDIM + tid];
    out_c[(size_t)b * HDIM + tid] = s;
}

// ---------------------------------------------------------------------------
extern "C" void kernel_launch(void* const* d_in, const int* in_sizes, int n_in,
                              void* d_out, int out_size) {
    const float* X   = (const float*)d_in[0];
    const float* Wxh = (const float*)d_in[1];
    const float* Whh = (const float*)d_in[2];
    const float* bh  = (const float*)d_in[3];
    const float* QW  = (const float*)d_in[4];
    const float* KW  = (const float*)d_in[5];
    float* Y = (float*)d_out;                                    // [T][B][H]
    float* out_c = Y + (size_t)T_STEPS * BATCH * HDIM;           // [B][H]

    init_kernel<<<64, 256>>>();
    xw_kernel<<<dim3(T_STEPS, 16), 256>>>(X, Wxh);
    dummy_kernel<<<1, 32>>>();     // position rnn_loop at the ncu capture slot
    rnn_loop<<<GCTA, RTHREADS>>>(Whh, bh, Y);
    att_q_kernel<<<BATCH, 256>>>(Y, QW, KW);
    att_scores_kernel<<<dim3(32, BATCH), 256>>>(Y);
    att_softmax_kernel<<<BATCH, 256>>>();
    att_ctx_kernel<<<dim3(8, BATCH), 256>>>(Y);
    att_ctx2_kernel<<<BATCH, 512>>>(out_c);
}

// round 6
// speedup vs baseline: 3.3181x; 1.0578x over previous
#include <cuda_runtime.h>
#include <math.h>

#define GCTA    64
#define RTHREADS 512
#define JPC     8
#define T_STEPS 2048
#define BATCH   32
#define HDIM    512
#define DIN     256

// ---- scratch (device globals; no allocation allowed) ----
__device__ float g_xw[(size_t)T_STEPS * HDIM * BATCH];   // [t][j][b], 134MB
__device__ float g_h[2][HDIM * BATCH];                   // ping-pong hidden state, [j][b]
__device__ float g_qh[BATCH * HDIM];                     // KW @ Q0
__device__ float g_sc[BATCH * T_STEPS];                  // scores
__device__ float g_att[BATCH * T_STEPS];                 // softmax weights
__device__ float g_cpart[8][BATCH * HDIM];               // context partials
__device__ __align__(128) unsigned g_flag[GCTA * 32];    // per-CTA arrive flags, 128B apart

// ---------------------------------------------------------------------------
__global__ void init_kernel() {
    int idx = blockIdx.x * blockDim.x + threadIdx.x;
    if (idx < HDIM * BATCH) g_h[0][idx] = 0.f;
    if (idx < GCTA) g_flag[idx * 32] = 0u;
}

__global__ void dummy_kernel() {}   // launch-position filler so ncu -s 5 lands on rnn_loop

// ---------------------------------------------------------------------------
// xw[t][j][b] = sum_d X[b][t][d] * Wxh[d][j]
__global__ __launch_bounds__(256) void xw_kernel(const float* __restrict__ X,
                                                 const float* __restrict__ Wxh) {
    __shared__ __align__(16) float Xs[128 * 33];  // [dl][b], padded
    __shared__ __align__(16) float Ws[128 * 32];  // [dl][jj]
    int t  = blockIdx.x;
    int j0 = blockIdx.y * 32;
    int tid = threadIdx.x;
    int warp = tid >> 5, lane = tid & 31;
    float acc0 = 0.f, acc1 = 0.f, acc2 = 0.f, acc3 = 0.f;

    for (int kp = 0; kp < 2; ++kp) {
        #pragma unroll
        for (int bb = 0; bb < 4; ++bb) {
            int b = warp * 4 + bb;
            const float* xp = X + ((size_t)b * T_STEPS + t) * DIN + kp * 128;
            #pragma unroll
            for (int it = 0; it < 4; ++it) {
                int dl = it * 32 + lane;
                Xs[dl * 33 + b] = xp[dl];
            }
        }
        for (int idx = tid; idx < 128 * 32; idx += 256) {
            int dl = idx >> 5, jj = idx & 31;
            Ws[idx] = Wxh[(size_t)(kp * 128 + dl) * HDIM + j0 + jj];
        }
        __syncthreads();
        #pragma unroll 8
        for (int dl = 0; dl < 128; ++dl) {
            float xv = Xs[dl * 33 + lane];
            float4 w = *(const float4*)&Ws[dl * 32 + warp * 4];
            acc0 += xv * w.x; acc1 += xv * w.y; acc2 += xv * w.z; acc3 += xv * w.w;
        }
        __syncthreads();
    }
    float* op = g_xw + ((size_t)t * HDIM + j0 + warp * 4) * BATCH + lane;
    op[0]  = acc0;
    op[32] = acc1;
    op[64] = acc2;
    op[96] = acc3;
}

// ---------------------------------------------------------------------------
// Persistent recurrence. 64 CTAs x 512 threads; CTA owns 8 consecutive j cols.
// Flat barrier: each CTA release-stores epoch t+1 to ITS OWN flag line (no
// atomics); warp 0 of every CTA polls all 64 flags in parallel (2 per lane).
// One L2 hop per step instead of arrive->publish->detect.
__global__ __launch_bounds__(RTHREADS) void rnn_loop(const float* __restrict__ Whh,
                                                     const float* __restrict__ bh,
                                                     float* __restrict__ Y) {
    __shared__ __align__(16) float Ws[HDIM * JPC];        // Whh[:, j0..j0+7], [i][c], 16KB
    __shared__ __align__(16) float red[JPC * RTHREADS];   // [c][warp][lane], 16KB
    int j0  = blockIdx.x * JPC;
    int tid = threadIdx.x;
    for (int idx = tid; idx < HDIM * JPC; idx += RTHREADS) {
        int i = idx >> 3, c = idx & 7;
        Ws[idx] = Whh[(size_t)i * HDIM + j0 + c];
    }
    int rb = tid & 31, rc = tid >> 5;          // final-phase thread -> (b, c), tid < 256
    float bias = (tid < 256) ? bh[j0 + rc] : 0.f;
    int warp = tid >> 5, lane = tid & 31;
    int i0 = warp * 32;
    unsigned* myflag = &g_flag[blockIdx.x * 32];
    unsigned* pf0 = &g_flag[lane * 32];          // poll targets for warp 0
    unsigned* pf1 = &g_flag[(lane + 32) * 32];
    __syncthreads();

    float xw_pref = (tid < 256) ? g_xw[((size_t)0 * HDIM + j0 + rc) * BATCH + rb] : 0.f;

    for (int t = 0; t < T_STEPS; ++t) {
        // ---- wait: all CTAs have published step t (flags >= t) ----
        if (t > 0) {
            if (tid < 32) {
                unsigned tgt = (unsigned)t, v;
                do { asm volatile("ld.relaxed.gpu.global.u32 %0, [%1];"
                                  : "=r"(v) : "l"(pf0)); } while (v < tgt);
                do { asm volatile("ld.relaxed.gpu.global.u32 %0, [%1];"
                                  : "=r"(v) : "l"(pf1)); } while (v < tgt);
                asm volatile("fence.acq_rel.gpu;" ::: "memory");
            }
            __syncthreads();
        }

        const float* hin = g_h[t & 1];
        float* hout = g_h[(t & 1) ^ 1];
        float a0=0.f,a1=0.f,a2=0.f,a3=0.f,a4=0.f,a5=0.f,a6=0.f,a7=0.f;
        const float* hp = hin + i0 * BATCH + lane;   // coalesced 128B rows
        #pragma unroll 8
        for (int i = 0; i < 32; ++i) {
            float hv = __ldcg(hp + i * BATCH);
            float4 w0 = *(const float4*)&Ws[(i0 + i) * JPC];
            float4 w1 = *(const float4*)&Ws[(i0 + i) * JPC + 4];
            a0 += hv * w0.x; a1 += hv * w0.y; a2 += hv * w0.z; a3 += hv * w0.w;
            a4 += hv * w1.x; a5 += hv * w1.y; a6 += hv * w1.z; a7 += hv * w1.w;
        }
        // conflict-free: red[c][warp][lane]
        red[0*RTHREADS + tid] = a0; red[1*RTHREADS + tid] = a1;
        red[2*RTHREADS + tid] = a2; red[3*RTHREADS + tid] = a3;
        red[4*RTHREADS + tid] = a4; red[5*RTHREADS + tid] = a5;
        red[6*RTHREADS + tid] = a6; red[7*RTHREADS + tid] = a7;
        __syncthreads();

        float hv_out = 0.f;
        if (tid < 256) {
            float s = bias + xw_pref;
            #pragma unroll
            for (int w = 0; w < 16; ++w) s += red[rc * RTHREADS + w * 32 + rb];
            hv_out = tanhf(s);
            __stcg(&hout[(j0 + rc) * BATCH + rb], hv_out);   // coalesced
        }
        __syncthreads();

        // ---- arrive: one release store to own flag line (no atomics) ----
        if (tid == 0) {
            asm volatile("fence.acq_rel.gpu;" ::: "memory");
            unsigned ep = (unsigned)(t + 1);
            asm volatile("st.relaxed.gpu.global.u32 [%0], %1;"
                         :: "l"(myflag), "r"(ep));
        }

        // ---- off-critical-path: Y output + xw prefetch for t+1 ----
        if (tid < 256) {
            Y[(size_t)t * (BATCH * HDIM) + (size_t)rb * HDIM + j0 + rc] = hv_out;
            if (t + 1 < T_STEPS)
                xw_pref = g_xw[((size_t)(t + 1) * HDIM + j0 + rc) * BATCH + rb];
        }
    }
}

// ---------------------------------------------------------------------------
// Q0[b] = Y[T-1,b] @ QW ; Qh[b] = KW @ Q0[b]   (one CTA per b)
__global__ __launch_bounds__(256) void att_q_kernel(const float* __restrict__ Y,
                                                    const float* __restrict__ QW,
                                                    const float* __restrict__ KW) {
    __shared__ float yT[HDIM];
    __shared__ float q0s[DIN];
    int b = blockIdx.x, tid = threadIdx.x;
    for (int h = tid; h < HDIM; h += 256)
        yT[h] = Y[(size_t)(T_STEPS - 1) * BATCH * HDIM + (size_t)b * HDIM + h];
    __syncthreads();
    float s = 0.f;
    for (int h = 0; h < HDIM; ++h) s += yT[h] * QW[(size_t)h * DIN + tid];
    q0s[tid] = s;
    __syncthreads();
    for (int j = tid; j < HDIM; j += 256) {
        float s2 = 0.f;
        const float* kp = KW + (size_t)j * DIN;
        #pragma unroll 4
        for (int d = 0; d < DIN; ++d) s2 += kp[d] * q0s[d];
        g_qh[b * HDIM + j] = s2;
    }
}

// scores[b][t] = tanh( Y[t,b,:] . Qh[b,:] )
__global__ __launch_bounds__(256) void att_scores_kernel(const float* __restrict__ Y) {
    __shared__ float qh[HDIM];
    int b = blockIdx.y, t0 = blockIdx.x * 64, tid = threadIdx.x;
    for (int h = tid; h < HDIM; h += 256) qh[h] = g_qh[b * HDIM + h];
    __syncthreads();
    int warp = tid >> 5, lane = tid & 31;
    for (int tt = warp; tt < 64; tt += 8) {
        int t = t0 + tt;
        const float* yp = Y + (size_t)t * BATCH * HDIM + (size_t)b * HDIM;
        float s = 0.f;
        #pragma unroll
        for (int it = 0; it < 16; ++it) s += yp[it * 32 + lane] * qh[it * 32 + lane];
        #pragma unroll
        for (int off = 16; off > 0; off >>= 1) s += __shfl_xor_sync(0xffffffffu, s, off);
        if (lane == 0) g_sc[b * T_STEPS + t] = tanhf(s);
    }
}

__global__ __launch_bounds__(256) void att_softmax_kernel() {
    __shared__ float sred[256];
    int b = blockIdx.x, tid = threadIdx.x;
    const float* sp = g_sc + b * T_STEPS;
    float m = -1e30f;
    for (int t = tid; t < T_STEPS; t += 256) m = fmaxf(m, sp[t]);
    sred[tid] = m; __syncthreads();
    for (int o = 128; o > 0; o >>= 1) {
        if (tid < o) sred[tid] = fmaxf(sred[tid], sred[tid + o]);
        __syncthreads();
    }
    m = sred[0]; __syncthreads();
    float sum = 0.f;
    for (int t = tid; t < T_STEPS; t += 256) sum += expf(sp[t] - m);
    sred[tid] = sum; __syncthreads();
    for (int o = 128; o > 0; o >>= 1) {
        if (tid < o) sred[tid] += sred[tid + o];
        __syncthreads();
    }
    float inv = 1.f / sred[0];
    for (int t = tid; t < T_STEPS; t += 256)
        g_att[b * T_STEPS + t] = expf(sp[t] - m) * inv;
}

// c partials: grid (8 t-chunks, 32 b)
__global__ __launch_bounds__(256) void att_ctx_kernel(const float* __restrict__ Y) {
    __shared__ float As[256];
    int tc = blockIdx.x, b = blockIdx.y, tid = threadIdx.x;
    As[tid] = g_att[b * T_STEPS + tc * 256 + tid];
    __syncthreads();
    float acc0 = 0.f, acc1 = 0.f;
    for (int tt = 0; tt < 256; ++tt) {
        const float* yp = Y + (size_t)(tc * 256 + tt) * BATCH * HDIM + (size_t)b * HDIM;
        float a = As[tt];
        acc0 += a * yp[tid];
        acc1 += a * yp[tid + 256];
    }
    g_cpart[tc][b * HDIM + tid]        = acc0;
    g_cpart[tc][b * HDIM + tid + 256]  = acc1;
}

__global__ __launch_bounds__(512) void att_ctx2_kernel(float* __restrict__ out_c) {
    int b = blockIdx.x, tid = threadIdx.x;
    float s = 0.f;
    #pragma unroll
    for (int p = 0; p < 8; ++p) s += g_cpart[p][b * HDIM + tid];
    out_c[(size_t)b * HDIM + tid] = s;
}

// ---------------------------------------------------------------------------
extern "C" void kernel_launch(void* const* d_in, const int* in_sizes, int n_in,
                              void* d_out, int out_size) {
    const float* X   = (const float*)d_in[0];
    const float* Wxh = (const float*)d_in[1];
    const float* Whh = (const float*)d_in[2];
    const float* bh  = (const float*)d_in[3];
    const float* QW  = (const float*)d_in[4];
    const float* KW  = (const float*)d_in[5];
    float* Y = (float*)d_out;                                    // [T][B][H]
    float* out_c = Y + (size_t)T_STEPS * BATCH * HDIM;           // [B][H]

    init_kernel<<<64, 256>>>();
    xw_kernel<<<dim3(T_STEPS, 16), 256>>>(X, Wxh);
    dummy_kernel<<<1, 32>>>();     // position rnn_loop at the ncu capture slot
    rnn_loop<<<GCTA, RTHREADS>>>(Whh, bh, Y);
    att_q_kernel<<<BATCH, 256>>>(Y, QW, KW);
    att_scores_kernel<<<dim3(32, BATCH), 256>>>(Y);
    att_softmax_kernel<<<BATCH, 256>>>();
    att_ctx_kernel<<<dim3(8, BATCH), 256>>>(Y);
    att_ctx2_kernel<<<BATCH, 512>>>(out_c);
}

// round 7
// speedup vs baseline: 4.2522x; 1.2815x over previous
#include <cuda_runtime.h>
#include <math.h>

#define GCTA    64
#define RTHREADS 512
#define JPC     8
#define T_STEPS 2048
#define BATCH   32
#define HDIM    512
#define DIN     256

// ---- scratch (device globals; no allocation allowed) ----
__device__ float g_xw[(size_t)T_STEPS * HDIM * BATCH];   // [t][j][b], 134MB
__device__ float g_h[2][HDIM * BATCH];                   // ping-pong hidden state, [j][b]
__device__ float g_qh[BATCH * HDIM];                     // KW @ Q0
__device__ float g_sc[BATCH * T_STEPS];                  // scores
__device__ float g_att[BATCH * T_STEPS];                 // softmax weights
__device__ float g_cpart[8][BATCH * HDIM];               // context partials
__device__ __align__(128) unsigned g_flag[GCTA * 32];    // per-CTA arrive flags, 128B apart

// ---------------------------------------------------------------------------
__global__ void init_kernel() {
    int idx = blockIdx.x * blockDim.x + threadIdx.x;
    if (idx < HDIM * BATCH) g_h[0][idx] = 0.f;
    if (idx < GCTA) g_flag[idx * 32] = 0u;
}

__global__ void dummy_kernel() {}   // launch-position filler so ncu -s 5 lands on rnn_loop

// ---------------------------------------------------------------------------
// xw[t][j][b] = sum_d X[b][t][d] * Wxh[d][j]
__global__ __launch_bounds__(256) void xw_kernel(const float* __restrict__ X,
                                                 const float* __restrict__ Wxh) {
    __shared__ __align__(16) float Xs[128 * 33];  // [dl][b], padded
    __shared__ __align__(16) float Ws[128 * 32];  // [dl][jj]
    int t  = blockIdx.x;
    int j0 = blockIdx.y * 32;
    int tid = threadIdx.x;
    int warp = tid >> 5, lane = tid & 31;
    float acc0 = 0.f, acc1 = 0.f, acc2 = 0.f, acc3 = 0.f;

    for (int kp = 0; kp < 2; ++kp) {
        #pragma unroll
        for (int bb = 0; bb < 4; ++bb) {
            int b = warp * 4 + bb;
            const float* xp = X + ((size_t)b * T_STEPS + t) * DIN + kp * 128;
            #pragma unroll
            for (int it = 0; it < 4; ++it) {
                int dl = it * 32 + lane;
                Xs[dl * 33 + b] = xp[dl];
            }
        }
        for (int idx = tid; idx < 128 * 32; idx += 256) {
            int dl = idx >> 5, jj = idx & 31;
            Ws[idx] = Wxh[(size_t)(kp * 128 + dl) * HDIM + j0 + jj];
        }
        __syncthreads();
        #pragma unroll 8
        for (int dl = 0; dl < 128; ++dl) {
            float xv = Xs[dl * 33 + lane];
            float4 w = *(const float4*)&Ws[dl * 32 + warp * 4];
            acc0 += xv * w.x; acc1 += xv * w.y; acc2 += xv * w.z; acc3 += xv * w.w;
        }
        __syncthreads();
    }
    float* op = g_xw + ((size_t)t * HDIM + j0 + warp * 4) * BATCH + lane;
    op[0]  = acc0;
    op[32] = acc1;
    op[64] = acc2;
    op[96] = acc3;
}

// ---------------------------------------------------------------------------
// Persistent recurrence. 64 CTAs x 512 threads; CTA owns 8 consecutive j cols.
// f32x2 packed FMA (2 MACs/instr), flat flag barrier, coalesced Y via staging.
__global__ __launch_bounds__(RTHREADS) void rnn_loop(const float* __restrict__ Whh,
                                                     const float* __restrict__ bh,
                                                     float* __restrict__ Y) {
    __shared__ __align__(16) float Ws[HDIM * JPC];        // [i][c], c=0..7, 16KB
    __shared__ __align__(16) float red[JPC * RTHREADS];   // [c][warp][lane], 16KB
    __shared__ float stage[32 * 9];                       // h_out staged [b][c], padded
    int j0  = blockIdx.x * JPC;
    int tid = threadIdx.x;
    for (int idx = tid; idx < HDIM * JPC; idx += RTHREADS) {
        int i = idx >> 3, c = idx & 7;
        Ws[idx] = Whh[(size_t)i * HDIM + j0 + c];
    }
    int rb = tid & 31, rc = tid >> 5;          // reducer mapping (tid < 256): b, c
    int sb = tid >> 3, sc = tid & 7;           // Y-writer mapping (tid < 256): b, c
    float bias = (tid < 256) ? bh[j0 + rc] : 0.f;
    int warp = tid >> 5, lane = tid & 31;
    int i0 = warp * 32;
    unsigned* myflag = &g_flag[blockIdx.x * 32];
    unsigned* pf0 = &g_flag[lane * 32];          // poll targets for warp 0
    unsigned* pf1 = &g_flag[(lane + 32) * 32];
    __syncthreads();

    float xw_pref = (tid < 256) ? g_xw[((size_t)0 * HDIM + j0 + rc) * BATCH + rb] : 0.f;

    for (int t = 0; t < T_STEPS; ++t) {
        // ---- wait: all CTAs have published step t (flags >= t) ----
        if (t > 0) {
            if (tid < 32) {
                unsigned tgt = (unsigned)t, v;
                do { asm volatile("ld.relaxed.gpu.global.u32 %0, [%1];"
                                  : "=r"(v) : "l"(pf0)); } while (v < tgt);
                do { asm volatile("ld.relaxed.gpu.global.u32 %0, [%1];"
                                  : "=r"(v) : "l"(pf1)); } while (v < tgt);
                asm volatile("fence.acq_rel.gpu;" ::: "memory");
            }
            __syncthreads();
        }

        const float* hin = g_h[t & 1];
        float* hout = g_h[(t & 1) ^ 1];
        // packed f32x2 accumulators: (j0+0,j0+1)(j0+2,j0+3)(j0+4,j0+5)(j0+6,j0+7)
        unsigned long long a01 = 0ull, a23 = 0ull, a45 = 0ull, a67 = 0ull;
        const float* hp = hin + i0 * BATCH + lane;   // coalesced 128B rows
        #pragma unroll 8
        for (int i = 0; i < 32; ++i) {
            float hv = __ldcg(hp + i * BATCH);
            unsigned long long hv2;
            asm("mov.b64 %0, {%1, %1};" : "=l"(hv2) : "f"(hv));
            ulonglong2 wA = *(const ulonglong2*)&Ws[(i0 + i) * JPC];      // j0..j3
            ulonglong2 wB = *(const ulonglong2*)&Ws[(i0 + i) * JPC + 4];  // j4..j7
            asm("fma.rn.f32x2 %0, %1, %2, %0;" : "+l"(a01) : "l"(hv2), "l"(wA.x));
            asm("fma.rn.f32x2 %0, %1, %2, %0;" : "+l"(a23) : "l"(hv2), "l"(wA.y));
            asm("fma.rn.f32x2 %0, %1, %2, %0;" : "+l"(a45) : "l"(hv2), "l"(wB.x));
            asm("fma.rn.f32x2 %0, %1, %2, %0;" : "+l"(a67) : "l"(hv2), "l"(wB.y));
        }
        {   // unpack and drop partials into smem (conflict-free: red[c][warp][lane])
            float p0,p1,p2,p3,p4,p5,p6,p7;
            asm("mov.b64 {%0, %1}, %2;" : "=f"(p0), "=f"(p1) : "l"(a01));
            asm("mov.b64 {%0, %1}, %2;" : "=f"(p2), "=f"(p3) : "l"(a23));
            asm("mov.b64 {%0, %1}, %2;" : "=f"(p4), "=f"(p5) : "l"(a45));
            asm("mov.b64 {%0, %1}, %2;" : "=f"(p6), "=f"(p7) : "l"(a67));
            red[0*RTHREADS + tid] = p0; red[1*RTHREADS + tid] = p1;
            red[2*RTHREADS + tid] = p2; red[3*RTHREADS + tid] = p3;
            red[4*RTHREADS + tid] = p4; red[5*RTHREADS + tid] = p5;
            red[6*RTHREADS + tid] = p6; red[7*RTHREADS + tid] = p7;
        }
        __syncthreads();

        if (tid < 256) {
            float s = bias + xw_pref;
            #pragma unroll
            for (int w = 0; w < 16; ++w) s += red[rc * RTHREADS + w * 32 + rb];
            float hv_out = tanhf(s);
            __stcg(&hout[(j0 + rc) * BATCH + rb], hv_out);   // coalesced 128B rows
            stage[rb * 9 + rc] = hv_out;                     // bank-conflict-free
        }
        __syncthreads();

        // ---- arrive: one release store to own flag line (cumulative) ----
        if (tid == 0) {
            unsigned ep = (unsigned)(t + 1);
            asm volatile("st.release.gpu.global.u32 [%0], %1;"
                         :: "l"(myflag), "r"(ep));
        }

        // ---- off-critical-path: coalesced Y output + xw prefetch for t+1 ----
        if (tid < 256) {
            Y[(size_t)t * (BATCH * HDIM) + (size_t)sb * HDIM + j0 + sc] = stage[sb * 9 + sc];
            if (t + 1 < T_STEPS)
                xw_pref = g_xw[((size_t)(t + 1) * HDIM + j0 + rc) * BATCH + rb];
        }
    }
}

// ---------------------------------------------------------------------------
// Q0[b] = Y[T-1,b] @ QW ; Qh[b] = KW @ Q0[b]   (one CTA per b)
__global__ __launch_bounds__(256) void att_q_kernel(const float* __restrict__ Y,
                                                    const float* __restrict__ QW,
                                                    const float* __restrict__ KW) {
    __shared__ float yT[HDIM];
    __shared__ float q0s[DIN];
    int b = blockIdx.x, tid = threadIdx.x;
    for (int h = tid; h < HDIM; h += 256)
        yT[h] = Y[(size_t)(T_STEPS - 1) * BATCH * HDIM + (size_t)b * HDIM + h];
    __syncthreads();
    float s = 0.f;
    for (int h = 0; h < HDIM; ++h) s += yT[h] * QW[(size_t)h * DIN + tid];
    q0s[tid] = s;
    __syncthreads();
    for (int j = tid; j < HDIM; j += 256) {
        float s2 = 0.f;
        const float* kp = KW + (size_t)j * DIN;
        #pragma unroll 4
        for (int d = 0; d < DIN; ++d) s2 += kp[d] * q0s[d];
        g_qh[b * HDIM + j] = s2;
    }
}

// scores[b][t] = tanh( Y[t,b,:] . Qh[b,:] )
__global__ __launch_bounds__(256) void att_scores_kernel(const float* __restrict__ Y) {
    __shared__ float qh[HDIM];
    int b = blockIdx.y, t0 = blockIdx.x * 64, tid = threadIdx.x;
    for (int h = tid; h < HDIM; h += 256) qh[h] = g_qh[b * HDIM + h];
    __syncthreads();
    int warp = tid >> 5, lane = tid & 31;
    for (int tt = warp; tt < 64; tt += 8) {
        int t = t0 + tt;
        const float* yp = Y + (size_t)t * BATCH * HDIM + (size_t)b * HDIM;
        float s = 0.f;
        #pragma unroll
        for (int it = 0; it < 16; ++it) s += yp[it * 32 + lane] * qh[it * 32 + lane];
        #pragma unroll
        for (int off = 16; off > 0; off >>= 1) s += __shfl_xor_sync(0xffffffffu, s, off);
        if (lane == 0) g_sc[b * T_STEPS + t] = tanhf(s);
    }
}

__global__ __launch_bounds__(256) void att_softmax_kernel() {
    __shared__ float sred[256];
    int b = blockIdx.x, tid = threadIdx.x;
    const float* sp = g_sc + b * T_STEPS;
    float m = -1e30f;
    for (int t = tid; t < T_STEPS; t += 256) m = fmaxf(m, sp[t]);
    sred[tid] = m; __syncthreads();
    for (int o = 128; o > 0; o >>= 1) {
        if (tid < o) sred[tid] = fmaxf(sred[tid], sred[tid + o]);
        __syncthreads();
    }
    m = sred[0]; __syncthreads();
    float sum = 0.f;
    for (int t = tid; t < T_STEPS; t += 256) sum += expf(sp[t] - m);
    sred[tid] = sum; __syncthreads();
    for (int o = 128; o > 0; o >>= 1) {
        if (tid < o) sred[tid] += sred[tid + o];
        __syncthreads();
    }
    float inv = 1.f / sred[0];
    for (int t = tid; t < T_STEPS; t += 256)
        g_att[b * T_STEPS + t] = expf(sp[t] - m) * inv;
}

// c partials: grid (8 t-chunks, 32 b)
__global__ __launch_bounds__(256) void att_ctx_kernel(const float* __restrict__ Y) {
    __shared__ float As[256];
    int tc = blockIdx.x, b = blockIdx.y, tid = threadIdx.x;
    As[tid] = g_att[b * T_STEPS + tc * 256 + tid];
    __syncthreads();
    float acc0 = 0.f, acc1 = 0.f;
    for (int tt = 0; tt < 256; ++tt) {
        const float* yp = Y + (size_t)(tc * 256 + tt) * BATCH * HDIM + (size_t)b * HDIM;
        float a = As[tt];
        acc0 += a * yp[tid];
        acc1 += a * yp[tid + 256];
    }
    g_cpart[tc][b * HDIM + tid]        = acc0;
    g_cpart[tc][b * HDIM + tid + 256]  = acc1;
}

__global__ __launch_bounds__(512) void att_ctx2_kernel(float* __restrict__ out_c) {
    int b = blockIdx.x, tid = threadIdx.x;
    float s = 0.f;
    #pragma unroll
    for (int p = 0; p < 8; ++p) s += g_cpart[p][b * HDIM + tid];
    out_c[(size_t)b * HDIM + tid] = s;
}

// ---------------------------------------------------------------------------
extern "C" void kernel_launch(void* const* d_in, const int* in_sizes, int n_in,
                              void* d_out, int out_size) {
    const float* X   = (const float*)d_in[0];
    const float* Wxh = (const float*)d_in[1];
    const float* Whh = (const float*)d_in[2];
    const float* bh  = (const float*)d_in[3];
    const float* QW  = (const float*)d_in[4];
    const float* KW  = (const float*)d_in[5];
    float* Y = (float*)d_out;                                    // [T][B][H]
    float* out_c = Y + (size_t)T_STEPS * BATCH * HDIM;           // [B][H]

    init_kernel<<<64, 256>>>();
    xw_kernel<<<dim3(T_STEPS, 16), 256>>>(X, Wxh);
    dummy_kernel<<<1, 32>>>();     // position rnn_loop at the ncu capture slot
    rnn_loop<<<GCTA, RTHREADS>>>(Whh, bh, Y);
    att_q_kernel<<<BATCH, 256>>>(Y, QW, KW);
    att_scores_kernel<<<dim3(32, BATCH), 256>>>(Y);
    att_softmax_kernel<<<BATCH, 256>>>();
    att_ctx_kernel<<<dim3(8, BATCH), 256>>>(Y);
    att_ctx2_kernel<<<BATCH, 512>>>(out_c);
}